// round 11
// baseline (speedup 1.0000x reference)
#include <cuda_runtime.h>
#include <cuda_fp16.h>
#include <cstdint>
#include <math.h>

#define BB 8
#define NN 2048
#define QQ 256
#define DD 1024
#define HH 16
#define HD 64

#define MQ (BB*QQ)   // 2048
#define MS (BB*NN)   // 16384

// Scratch (device globals; no allocation allowed)
__device__ float g_q[MQ*DD];
__device__ float g_k[MS*DD];
__device__ float g_v[MS*DD];
__device__ float g_o[MQ*DD];

// ---------------------------------------------------------------------------
// helpers
// ---------------------------------------------------------------------------
__device__ __forceinline__ uint32_t pack2h(float a, float b) {
    __half2 h = __floats2half2_rn(a, b);   // low = a, high = b
    return *reinterpret_cast<uint32_t*>(&h);
}

__device__ __forceinline__ void mma16(float* c, const uint32_t* a, const uint32_t* b) {
    asm volatile("mma.sync.aligned.m16n8k16.row.col.f32.f16.f16.f32 "
        "{%0,%1,%2,%3}, {%4,%5,%6,%7}, {%8,%9}, {%0,%1,%2,%3};"
        : "+f"(c[0]), "+f"(c[1]), "+f"(c[2]), "+f"(c[3])
        : "r"(a[0]), "r"(a[1]), "r"(a[2]), "r"(a[3]), "r"(b[0]), "r"(b[1]));
}

__device__ __forceinline__ uint32_t smem_u32(const void* p) {
    uint32_t r;
    asm("{ .reg .u64 t; cvta.to.shared.u64 t, %1; cvt.u32.u64 %0, t; }" : "=r"(r) : "l"(p));
    return r;
}

__device__ __forceinline__ void ldmatrix_x4(uint32_t* r, uint32_t addr) {
    asm volatile("ldmatrix.sync.aligned.m8n8.x4.shared.b16 {%0,%1,%2,%3}, [%4];"
        : "=r"(r[0]), "=r"(r[1]), "=r"(r[2]), "=r"(r[3]) : "r"(addr));
}

__device__ __forceinline__ void ldmatrix_x4_trans(uint32_t* r, uint32_t addr) {
    asm volatile("ldmatrix.sync.aligned.m8n8.x4.trans.shared.b16 {%0,%1,%2,%3}, [%4];"
        : "=r"(r[0]), "=r"(r[1]), "=r"(r[2]), "=r"(r[3]) : "r"(addr));
}

// ---------------------------------------------------------------------------
// FP16 mma.sync GEMM-NT with ldmatrix fragment loads.
// C[M,N] = A[M,K] @ W[N,K]^T + bias (+ residual)
// CTA tile 128x128, K chunk 32, 8 warps (2m x 4n) of 64x32.
// smem: halfs in k-pair words, 16 words data per row, row stride 20 words
//  -> every ldmatrix 8-row phase hits banks {20r mod 32} = all 32 banks once.
// ---------------------------------------------------------------------------
#define KCH 32
#define GRS 20                    // row stride in 32-bit words
#define GTW (128*GRS)             // tile words (2560)
#define SMEM_GEMM (4*GTW*4)       // A0,B0,A1,B1 -> 40960 bytes

template<bool RESIDUAL>
__global__ __launch_bounds__(256, 1)
void gemm_h(const float* __restrict__ A, const float* __restrict__ W,
            const float* __restrict__ bias, const float* __restrict__ res,
            float* __restrict__ C, int M, int N, int K)
{
    extern __shared__ uint32_t swm[];
    uint32_t* bufA[2] = { swm,           swm + 2 * GTW };
    uint32_t* bufB[2] = { swm + GTW,     swm + 3 * GTW };
    const uint32_t sbase = smem_u32(swm);

    const int tid  = threadIdx.x;
    const int wid  = tid >> 5;
    const int lane = tid & 31;
    const int gid  = lane >> 2;
    const int tg   = lane & 3;
    const int wm   = wid >> 2;
    const int wn   = wid & 3;
    const int m0 = blockIdx.y * 128;
    const int n0 = blockIdx.x * 128;

    const int wrow = tid >> 3;
    const int q4   = tid & 7;

    // ldmatrix source addresses (byte offsets into a tile, lane-dependent)
    // A fragment (m16k16): rows wm*64 + mt*16 + (lane&15), k-block (lane>>4)*8 halfs
    const uint32_t aRow = (uint32_t)(wm * 64 + (lane & 15));
    const uint32_t aCol = (uint32_t)((lane >> 4) << 2);               // words
    // B fragment (x4 over both ks): rows wn*32 + nt*8 + (lane&7), word (lane>>3)*4
    const uint32_t bRow = (uint32_t)(wn * 32 + (lane & 7));
    const uint32_t bCol = (uint32_t)((lane >> 3) << 2);               // words

    float acc[4][4][4];
#pragma unroll
    for (int i = 0; i < 4; i++)
#pragma unroll
        for (int j = 0; j < 4; j++)
#pragma unroll
            for (int r = 0; r < 4; r++) acc[i][j][r] = 0.f;

    float4 ra[4], rb[4];
    const int nch = K / KCH;

    // prologue: load + store chunk 0
#pragma unroll
    for (int i = 0; i < 4; i++) {
        int row = wrow + 32 * i;
        ra[i] = *reinterpret_cast<const float4*>(&A[(size_t)(m0 + row) * K + q4 * 4]);
        rb[i] = *reinterpret_cast<const float4*>(&W[(size_t)(n0 + row) * K + q4 * 4]);
    }
#pragma unroll
    for (int i = 0; i < 4; i++) {
        int row = wrow + 32 * i;
        uint2 ua = { pack2h(ra[i].x, ra[i].y), pack2h(ra[i].z, ra[i].w) };
        uint2 ub = { pack2h(rb[i].x, rb[i].y), pack2h(rb[i].z, rb[i].w) };
        *reinterpret_cast<uint2*>(&bufA[0][row * GRS + q4 * 2]) = ua;
        *reinterpret_cast<uint2*>(&bufB[0][row * GRS + q4 * 2]) = ub;
    }
    __syncthreads();

    for (int c = 0; c < nch; c++) {
        const int buf = c & 1;
        if (c + 1 < nch) {
            const int kc = (c + 1) * KCH;
#pragma unroll
            for (int i = 0; i < 4; i++) {
                int row = wrow + 32 * i;
                ra[i] = *reinterpret_cast<const float4*>(&A[(size_t)(m0 + row) * K + kc + q4 * 4]);
                rb[i] = *reinterpret_cast<const float4*>(&W[(size_t)(n0 + row) * K + kc + q4 * 4]);
            }
        }
        const uint32_t aTile = sbase + (buf ? 2 * GTW * 4 : 0);
        const uint32_t bTile = sbase + (buf ? 3 * GTW * 4 : GTW * 4);

        // B fragments: one ldmatrix.x4 per nt covers both k16 steps
        uint32_t bq[4][4];
#pragma unroll
        for (int nt = 0; nt < 4; nt++) {
            uint32_t addr = bTile + ((bRow + nt * 8) * GRS + bCol) * 4;
            ldmatrix_x4(bq[nt], addr);
        }
#pragma unroll
        for (int ks = 0; ks < 2; ks++) {
            uint32_t af[4][4];
#pragma unroll
            for (int mt = 0; mt < 4; mt++) {
                uint32_t addr = aTile + ((aRow + mt * 16) * GRS + ks * 8 + aCol) * 4;
                ldmatrix_x4(af[mt], addr);
            }
#pragma unroll
            for (int mt = 0; mt < 4; mt++)
#pragma unroll
                for (int nt = 0; nt < 4; nt++)
                    mma16(acc[mt][nt], af[mt], &bq[nt][2 * ks]);
        }
        if (c + 1 < nch) {
            uint32_t* nA = bufA[buf ^ 1];
            uint32_t* nB = bufB[buf ^ 1];
#pragma unroll
            for (int i = 0; i < 4; i++) {
                int row = wrow + 32 * i;
                uint2 ua = { pack2h(ra[i].x, ra[i].y), pack2h(ra[i].z, ra[i].w) };
                uint2 ub = { pack2h(rb[i].x, rb[i].y), pack2h(rb[i].z, rb[i].w) };
                *reinterpret_cast<uint2*>(&nA[row * GRS + q4 * 2]) = ua;
                *reinterpret_cast<uint2*>(&nB[row * GRS + q4 * 2]) = ub;
            }
            __syncthreads();
        }
    }

    // epilogue
#pragma unroll
    for (int mt = 0; mt < 4; mt++) {
#pragma unroll
        for (int nt = 0; nt < 4; nt++) {
            int row = m0 + wm * 64 + mt * 16 + gid;
            int col = n0 + wn * 32 + nt * 8 + tg * 2;
            float2 bv = *reinterpret_cast<const float2*>(&bias[col]);
            float2 o0 = { acc[mt][nt][0] + bv.x, acc[mt][nt][1] + bv.y };
            float2 o1 = { acc[mt][nt][2] + bv.x, acc[mt][nt][3] + bv.y };
            if (RESIDUAL) {
                float2 r0 = *reinterpret_cast<const float2*>(&res[(size_t)row * N + col]);
                float2 r1 = *reinterpret_cast<const float2*>(&res[(size_t)(row + 8) * N + col]);
                o0.x += r0.x; o0.y += r0.y;
                o1.x += r1.x; o1.y += r1.y;
            }
            *reinterpret_cast<float2*>(&C[(size_t)row * N + col]) = o0;
            *reinterpret_cast<float2*>(&C[(size_t)(row + 8) * N + col]) = o1;
        }
    }
}

// ---------------------------------------------------------------------------
// FP16 tensor-core flash attention (unchanged from round 4, known good).
// ---------------------------------------------------------------------------
#define ARS 36
#define ATW (64*ARS)
#define SMEM_ATTN (5*ATW*4)

__global__ __launch_bounds__(128, 1)
void attn_h(const float* __restrict__ q, const float* __restrict__ k,
            const float* __restrict__ v, float* __restrict__ o)
{
    extern __shared__ uint32_t swm[];
    uint32_t* Qs = swm;
    uint32_t* Ks[2] = { swm + ATW, swm + 2 * ATW };
    uint32_t* Vs[2] = { swm + 3 * ATW, swm + 4 * ATW };
    const uint32_t sbase = smem_u32(swm);

    const int tid  = threadIdx.x;
    const int wid  = tid >> 5;
    const int lane = tid & 31;
    const int gid  = lane >> 2;
    const int tg   = lane & 3;
    const int b  = blockIdx.y / HH;
    const int h  = blockIdx.y % HH;
    const int q0 = blockIdx.x * 64;

    const int lrow = tid >> 4;
    const int lc4  = tid & 15;

    const float scale = 0.125f;

#pragma unroll
    for (int i = 0; i < 8; i++) {
        int row = lrow + 8 * i;
        float4 vq = *reinterpret_cast<const float4*>(
            &q[((size_t)(b * QQ + q0 + row)) * DD + h * HD + lc4 * 4]);
        uint2 u = { pack2h(vq.x * scale, vq.y * scale), pack2h(vq.z * scale, vq.w * scale) };
        *reinterpret_cast<uint2*>(&Qs[row * ARS + lc4 * 2]) = u;

        size_t kb = ((size_t)(b * NN + row)) * DD + h * HD + lc4 * 4;
        float4 vk = *reinterpret_cast<const float4*>(&k[kb]);
        float4 vv = *reinterpret_cast<const float4*>(&v[kb]);
        *reinterpret_cast<uint2*>(&Ks[0][row * ARS + lc4 * 2]) =
            make_uint2(pack2h(vk.x, vk.y), pack2h(vk.z, vk.w));
        *reinterpret_cast<uint2*>(&Vs[0][row * ARS + lc4 * 2]) =
            make_uint2(pack2h(vv.x, vv.y), pack2h(vv.z, vv.w));
    }
    __syncthreads();

    uint32_t qa[4][4];
#pragma unroll
    for (int ks = 0; ks < 4; ks++) {
        int r = (wid * 16 + gid) * ARS + ks * 8 + tg;
        qa[ks][0] = Qs[r];
        qa[ks][1] = Qs[r + 8 * ARS];
        qa[ks][2] = Qs[r + 4];
        qa[ks][3] = Qs[r + 8 * ARS + 4];
    }

    float m0 = -1e30f, m1 = -1e30f, l0 = 0.f, l1 = 0.f;
    float oacc[8][4];
#pragma unroll
    for (int nt = 0; nt < 8; nt++)
#pragma unroll
        for (int r = 0; r < 4; r++) oacc[nt][r] = 0.f;

    for (int t = 0; t < NN / 64; t++) {
        const int buf = t & 1;
        if (t + 1 < NN / 64) {
            const int nb = buf ^ 1;
            const int n1 = (t + 1) * 64;
#pragma unroll
            for (int i = 0; i < 8; i++) {
                int row = lrow + 8 * i;
                size_t kb = ((size_t)(b * NN + n1 + row)) * DD + h * HD + lc4 * 4;
                float4 vk = *reinterpret_cast<const float4*>(&k[kb]);
                float4 vv = *reinterpret_cast<const float4*>(&v[kb]);
                *reinterpret_cast<uint2*>(&Ks[nb][row * ARS + lc4 * 2]) =
                    make_uint2(pack2h(vk.x, vk.y), pack2h(vk.z, vk.w));
                *reinterpret_cast<uint2*>(&Vs[nb][row * ARS + lc4 * 2]) =
                    make_uint2(pack2h(vv.x, vv.y), pack2h(vv.z, vv.w));
            }
        }

        float s[8][4];
#pragma unroll
        for (int nt = 0; nt < 8; nt++)
#pragma unroll
            for (int r = 0; r < 4; r++) s[nt][r] = 0.f;
#pragma unroll
        for (int ks = 0; ks < 4; ks++) {
#pragma unroll
            for (int nt = 0; nt < 8; nt++) {
                int r = (nt * 8 + gid) * ARS + ks * 8 + tg;
                uint32_t bf[2] = { Ks[buf][r], Ks[buf][r + 4] };
                mma16(s[nt], qa[ks], bf);
            }
        }

        float mx0 = -1e30f, mx1 = -1e30f;
#pragma unroll
        for (int nt = 0; nt < 8; nt++) {
            mx0 = fmaxf(mx0, fmaxf(s[nt][0], s[nt][1]));
            mx1 = fmaxf(mx1, fmaxf(s[nt][2], s[nt][3]));
        }
        mx0 = fmaxf(mx0, __shfl_xor_sync(0xffffffffu, mx0, 1));
        mx0 = fmaxf(mx0, __shfl_xor_sync(0xffffffffu, mx0, 2));
        mx1 = fmaxf(mx1, __shfl_xor_sync(0xffffffffu, mx1, 1));
        mx1 = fmaxf(mx1, __shfl_xor_sync(0xffffffffu, mx1, 2));
        float mn0 = fmaxf(m0, mx0), mn1 = fmaxf(m1, mx1);
        float a0 = __expf(m0 - mn0), a1 = __expf(m1 - mn1);
        m0 = mn0; m1 = mn1;
        float sum0 = 0.f, sum1 = 0.f;
#pragma unroll
        for (int nt = 0; nt < 8; nt++) {
            s[nt][0] = __expf(s[nt][0] - m0);
            s[nt][1] = __expf(s[nt][1] - m0);
            s[nt][2] = __expf(s[nt][2] - m1);
            s[nt][3] = __expf(s[nt][3] - m1);
            sum0 += s[nt][0] + s[nt][1];
            sum1 += s[nt][2] + s[nt][3];
        }
        sum0 += __shfl_xor_sync(0xffffffffu, sum0, 1);
        sum0 += __shfl_xor_sync(0xffffffffu, sum0, 2);
        sum1 += __shfl_xor_sync(0xffffffffu, sum1, 1);
        sum1 += __shfl_xor_sync(0xffffffffu, sum1, 2);
        l0 = l0 * a0 + sum0;
        l1 = l1 * a1 + sum1;
#pragma unroll
        for (int nt = 0; nt < 8; nt++) {
            oacc[nt][0] *= a0; oacc[nt][1] *= a0;
            oacc[nt][2] *= a1; oacc[nt][3] *= a1;
        }

        const uint32_t vs0 = sbase + ((3 + buf) * ATW) * 4;
#pragma unroll
        for (int ks = 0; ks < 4; ks++) {
            uint32_t pa[4];
            pa[0] = pack2h(s[2 * ks][0],     s[2 * ks][1]);
            pa[1] = pack2h(s[2 * ks][2],     s[2 * ks][3]);
            pa[2] = pack2h(s[2 * ks + 1][0], s[2 * ks + 1][1]);
            pa[3] = pack2h(s[2 * ks + 1][2], s[2 * ks + 1][3]);
#pragma unroll
            for (int ntp = 0; ntp < 4; ntp++) {
                uint32_t vb[4];
                uint32_t addr = vs0 +
                    ((16 * ks + (lane & 15)) * ARS + 8 * ntp + ((lane >> 4) << 2)) * 4;
                ldmatrix_x4_trans(vb, addr);
                mma16(oacc[2 * ntp],     pa, vb);
                mma16(oacc[2 * ntp + 1], pa, vb + 2);
            }
        }
        __syncthreads();
    }

    float r0 = 1.f / l0, r1 = 1.f / l1;
    int row0 = b * QQ + q0 + wid * 16 + gid;
#pragma unroll
    for (int nt = 0; nt < 8; nt++) {
        int col = h * HD + nt * 8 + tg * 2;
        float2 v0 = { oacc[nt][0] * r0, oacc[nt][1] * r0 };
        float2 v1 = { oacc[nt][2] * r1, oacc[nt][3] * r1 };
        *reinterpret_cast<float2*>(&o[(size_t)row0 * DD + col]) = v0;
        *reinterpret_cast<float2*>(&o[(size_t)(row0 + 8) * DD + col]) = v1;
    }
}

// ---------------------------------------------------------------------------
extern "C" void kernel_launch(void* const* d_in, const int* in_sizes, int n_in,
                              void* d_out, int out_size)
{
    const float* sources = (const float*)d_in[0];
    const float* queries = (const float*)d_in[1];
    const float* w_in    = (const float*)d_in[2];
    const float* b_in    = (const float*)d_in[3];
    const float* w_out   = (const float*)d_in[4];
    const float* b_out   = (const float*)d_in[5];
    float* out = (float*)d_out;

    float *pq, *pk, *pv, *po;
    cudaGetSymbolAddress((void**)&pq, g_q);
    cudaGetSymbolAddress((void**)&pk, g_k);
    cudaGetSymbolAddress((void**)&pv, g_v);
    cudaGetSymbolAddress((void**)&po, g_o);

    cudaFuncSetAttribute(gemm_h<false>, cudaFuncAttributeMaxDynamicSharedMemorySize, SMEM_GEMM);
    cudaFuncSetAttribute(gemm_h<true>,  cudaFuncAttributeMaxDynamicSharedMemorySize, SMEM_GEMM);
    cudaFuncSetAttribute(attn_h, cudaFuncAttributeMaxDynamicSharedMemorySize, SMEM_ATTN);

    // Q projection
    gemm_h<false><<<dim3(DD / 128, MQ / 128), 256, SMEM_GEMM>>>(queries, w_in, b_in, nullptr, pq, MQ, DD, DD);
    // K projection
    gemm_h<false><<<dim3(DD / 128, MS / 128), 256, SMEM_GEMM>>>(sources, w_in + DD * DD, b_in + DD, nullptr, pk, MS, DD, DD);
    // V projection
    gemm_h<false><<<dim3(DD / 128, MS / 128), 256, SMEM_GEMM>>>(sources, w_in + 2 * DD * DD, b_in + 2 * DD, nullptr, pv, MS, DD, DD);
    // attention
    attn_h<<<dim3(QQ / 64, BB * HH), 128, SMEM_ATTN>>>(pq, pk, pv, po);
    // out projection + bias + residual
    gemm_h<true><<<dim3(DD / 128, MQ / 128), 256, SMEM_GEMM>>>(po, w_out, b_out, queries, out, MQ, DD, DD);
}

// round 15
// speedup vs baseline: 1.6894x; 1.6894x over previous
#include <cuda_runtime.h>
#include <cuda_fp16.h>
#include <cstdint>
#include <math.h>

#define BB 8
#define NN 2048
#define QQ 256
#define DD 1024
#define HH 16
#define HD 64

#define MQ (BB*QQ)   // 2048
#define MS (BB*NN)   // 16384

// Scratch (device globals; no allocation allowed)
__device__ __half g_qh[MQ*DD];      // Q projection out
__device__ __half g_kh[MS*DD];      // K projection out
__device__ __half g_vh[MS*DD];      // V projection out
__device__ __half g_oh[MQ*DD];      // attention out
__device__ __half g_srch[MS*DD];    // sources fp16
__device__ __half g_qryh[MQ*DD];    // queries fp16
__device__ __half g_wh[3*DD*DD];    // w_in fp16
__device__ __half g_woh[DD*DD];     // w_out fp16

// ---------------------------------------------------------------------------
// helpers
// ---------------------------------------------------------------------------
__device__ __forceinline__ uint32_t pack2h(float a, float b) {
    __half2 h = __floats2half2_rn(a, b);
    return *reinterpret_cast<uint32_t*>(&h);
}

__device__ __forceinline__ uint32_t hmul2u(uint32_t a, uint32_t b) {
    uint32_t d;
    asm("mul.f16x2 %0, %1, %2;" : "=r"(d) : "r"(a), "r"(b));
    return d;
}

__device__ __forceinline__ void mma16(float* c, const uint32_t* a, const uint32_t* b) {
    asm volatile("mma.sync.aligned.m16n8k16.row.col.f32.f16.f16.f32 "
        "{%0,%1,%2,%3}, {%4,%5,%6,%7}, {%8,%9}, {%0,%1,%2,%3};"
        : "+f"(c[0]), "+f"(c[1]), "+f"(c[2]), "+f"(c[3])
        : "r"(a[0]), "r"(a[1]), "r"(a[2]), "r"(a[3]), "r"(b[0]), "r"(b[1]));
}

__device__ __forceinline__ uint32_t smem_u32(const void* p) {
    uint32_t r;
    asm("{ .reg .u64 t; cvta.to.shared.u64 t, %1; cvt.u32.u64 %0, t; }" : "=r"(r) : "l"(p));
    return r;
}

__device__ __forceinline__ void ldmatrix_x4(uint32_t* r, uint32_t addr) {
    asm volatile("ldmatrix.sync.aligned.m8n8.x4.shared.b16 {%0,%1,%2,%3}, [%4];"
        : "=r"(r[0]), "=r"(r[1]), "=r"(r[2]), "=r"(r[3]) : "r"(addr));
}

__device__ __forceinline__ void ldmatrix_x4_trans(uint32_t* r, uint32_t addr) {
    asm volatile("ldmatrix.sync.aligned.m8n8.x4.trans.shared.b16 {%0,%1,%2,%3}, [%4];"
        : "=r"(r[0]), "=r"(r[1]), "=r"(r[2]), "=r"(r[3]) : "r"(addr));
}

__device__ __forceinline__ void cp16(uint32_t saddr, const void* g) {
    asm volatile("cp.async.cg.shared.global [%0], [%1], 16;" :: "r"(saddr), "l"(g));
}
__device__ __forceinline__ void cp_commit() {
    asm volatile("cp.async.commit_group;" ::: "memory");
}
template<int N> __device__ __forceinline__ void cp_wait() {
    asm volatile("cp.async.wait_group %0;" :: "n"(N) : "memory");
}

// ---------------------------------------------------------------------------
// fp32 -> fp16 convert pass
// ---------------------------------------------------------------------------
__global__ __launch_bounds__(256)
void cvt_f2h(const float* __restrict__ src, __half* __restrict__ dst, int n)
{
    int i = (blockIdx.x * 256 + threadIdx.x) * 4;
    if (i < n) {
        float4 v = *reinterpret_cast<const float4*>(src + i);
        uint2 u = { pack2h(v.x, v.y), pack2h(v.z, v.w) };
        *reinterpret_cast<uint2*>(dst + i) = u;
    }
}

// ---------------------------------------------------------------------------
// FP16 GEMM-NT, cp.async 4-stage pipeline + ldmatrix + mma.sync.
// C[M,N] = A[M,K] @ W[N,K]^T + bias (+ residual). A, W fp16; C fp16 or fp32.
// CTA tile 128x128, K chunk 32 halfs, 8 warps (2m x 4n) of 64x32.
// smem rows: 32 halfs data (64B), row stride 20 words (80B) -> ldmatrix
// 8-row phases hit banks {20r mod 32} = all 32 banks exactly once.
// ---------------------------------------------------------------------------
#define KCH 32
#define GRS 20                    // row stride, 32-bit words
#define GTW (128*GRS)             // words per tile (2560)
#define STG_W (2*GTW)             // A+B words per stage
#define STAGES 4
#define SMEM_GEMM (STAGES*STG_W*4)   // 81920 bytes

template<bool OUTH, bool RESIDUAL>
__global__ __launch_bounds__(256, 2)
void gemm_h2(const __half* __restrict__ A, const __half* __restrict__ W,
             const float* __restrict__ bias, const float* __restrict__ res,
             void* __restrict__ Cv, int M, int N, int K)
{
    extern __shared__ uint32_t swm[];
    const uint32_t sbase = smem_u32(swm);

    const int tid  = threadIdx.x;
    const int wid  = tid >> 5;
    const int lane = tid & 31;
    const int gid  = lane >> 2;
    const int tg   = lane & 3;
    const int wm   = wid >> 2;
    const int wn   = wid & 3;
    const int m0 = blockIdx.y * 128;
    const int n0 = blockIdx.x * 128;

    // cp.async chunk indexing: 512 chunks of 16B per tile (128 rows x 4)
    const int crow0 = tid >> 2;          // rows tid>>2 and +64
    const int cc4   = tid & 3;           // 16B chunk in row

    // ldmatrix lane addressing
    const uint32_t aRow = (uint32_t)(wm * 64 + (lane & 15));
    const uint32_t aCol = (uint32_t)((lane >> 4) << 2);
    const uint32_t bRow = (uint32_t)(wn * 32 + (lane & 7));
    const uint32_t bCol = (uint32_t)((lane >> 3) << 2);

    float acc[4][4][4];
#pragma unroll
    for (int i = 0; i < 4; i++)
#pragma unroll
        for (int j = 0; j < 4; j++)
#pragma unroll
            for (int r = 0; r < 4; r++) acc[i][j][r] = 0.f;

    const int nch = K / KCH;

    // issue one stage of cp.asyncs (no commit)
    auto issue = [&](int c) {
        const int st = c & (STAGES - 1);
        const uint32_t sA = sbase + st * (STG_W * 4);
        const uint32_t sB = sA + GTW * 4;
        const __half* Ap = A + (size_t)m0 * K + c * KCH;
        const __half* Wp = W + (size_t)n0 * K + c * KCH;
#pragma unroll
        for (int i = 0; i < 2; i++) {
            int row = crow0 + i * 64;
            cp16(sA + row * 80 + cc4 * 16, Ap + (size_t)row * K + cc4 * 8);
            cp16(sB + row * 80 + cc4 * 16, Wp + (size_t)row * K + cc4 * 8);
        }
    };

    // prologue: stages 0..STAGES-2
#pragma unroll
    for (int s = 0; s < STAGES - 1; s++) {
        issue(s);
        cp_commit();
    }

    for (int c = 0; c < nch; c++) {
        cp_wait<STAGES - 2>();
        __syncthreads();

        const int st = c & (STAGES - 1);
        const uint32_t aTile = sbase + st * (STG_W * 4);
        const uint32_t bTile = aTile + GTW * 4;

        uint32_t bq[4][4];
#pragma unroll
        for (int nt = 0; nt < 4; nt++)
            ldmatrix_x4(bq[nt], bTile + ((bRow + nt * 8) * GRS + bCol) * 4);
#pragma unroll
        for (int ks = 0; ks < 2; ks++) {
            uint32_t af[4][4];
#pragma unroll
            for (int mt = 0; mt < 4; mt++)
                ldmatrix_x4(af[mt], aTile + ((aRow + mt * 16) * GRS + ks * 8 + aCol) * 4);
#pragma unroll
            for (int mt = 0; mt < 4; mt++)
#pragma unroll
                for (int nt = 0; nt < 4; nt++)
                    mma16(acc[mt][nt], af[mt], &bq[nt][2 * ks]);
        }

        // issue stage c+STAGES-1 (targets the buffer computed LAST iteration;
        // all threads passed this iteration's __syncthreads -> safe)
        if (c + STAGES - 1 < nch) issue(c + STAGES - 1);
        cp_commit();   // always commit (possibly empty) to keep group accounting
    }

    // epilogue
#pragma unroll
    for (int mt = 0; mt < 4; mt++) {
#pragma unroll
        for (int nt = 0; nt < 4; nt++) {
            int row = m0 + wm * 64 + mt * 16 + gid;
            int col = n0 + wn * 32 + nt * 8 + tg * 2;
            float2 bv = *reinterpret_cast<const float2*>(&bias[col]);
            float2 o0 = { acc[mt][nt][0] + bv.x, acc[mt][nt][1] + bv.y };
            float2 o1 = { acc[mt][nt][2] + bv.x, acc[mt][nt][3] + bv.y };
            if (RESIDUAL) {
                float2 r0 = *reinterpret_cast<const float2*>(&res[(size_t)row * N + col]);
                float2 r1 = *reinterpret_cast<const float2*>(&res[(size_t)(row + 8) * N + col]);
                o0.x += r0.x; o0.y += r0.y;
                o1.x += r1.x; o1.y += r1.y;
            }
            if (OUTH) {
                __half* Ch = (__half*)Cv;
                *reinterpret_cast<uint32_t*>(&Ch[(size_t)row * N + col]) = pack2h(o0.x, o0.y);
                *reinterpret_cast<uint32_t*>(&Ch[(size_t)(row + 8) * N + col]) = pack2h(o1.x, o1.y);
            } else {
                float* Cf = (float*)Cv;
                *reinterpret_cast<float2*>(&Cf[(size_t)row * N + col]) = o0;
                *reinterpret_cast<float2*>(&Cf[(size_t)(row + 8) * N + col]) = o1;
            }
        }
    }
}

// ---------------------------------------------------------------------------
// FP16 tensor-core flash attention, fp16 in/out, cp.async K/V prefetch.
// CTA = 64 queries x one (b,h); 4 warps x 16 q-rows.
// smem rows: 64 halfs (128B), stride 36 words (144B) -> conflict-free
// ldmatrix (banks 4r mod 32 per 8-row phase).
// ---------------------------------------------------------------------------
#define ARS 36
#define ATW (64*ARS)
#define SMEM_ATTN (5*ATW*4)       // Qs | Ks0 | Ks1 | Vs0 | Vs1 = 46080 B

__global__ __launch_bounds__(128, 1)
void attn_h2(const __half* __restrict__ q, const __half* __restrict__ k,
             const __half* __restrict__ v, __half* __restrict__ o)
{
    extern __shared__ uint32_t swm[];
    const uint32_t sbase = smem_u32(swm);
    const uint32_t qBase = sbase;
    const uint32_t kBase[2] = { sbase + ATW * 4, sbase + 2 * ATW * 4 };
    const uint32_t vBase[2] = { sbase + 3 * ATW * 4, sbase + 4 * ATW * 4 };

    const int tid  = threadIdx.x;
    const int wid  = tid >> 5;
    const int lane = tid & 31;
    const int gid  = lane >> 2;
    const int tg   = lane & 3;
    const int b  = blockIdx.y / HH;
    const int h  = blockIdx.y % HH;
    const int q0 = blockIdx.x * 64;

    // loader indexing: 64 rows x 8 chunks of 16B; 128 threads -> 4 per array
    const int lrow = tid >> 1;           // not used directly; see below

    // ---- load Q tile (plain uint4), issue cp.async for K/V tile 0 ----
#pragma unroll
    for (int i = 0; i < 4; i++) {
        int idx = tid + i * 128;         // 0..511
        int row = idx >> 3, c8 = idx & 7;
        uint4 u = *reinterpret_cast<const uint4*>(
            &q[((size_t)(b * QQ + q0 + row)) * DD + h * HD + c8 * 8]);
        *reinterpret_cast<uint4*>(
            reinterpret_cast<char*>(swm) + row * 144 + c8 * 16) = u;
    }
    {
        const __half* kp = k + ((size_t)b * NN) * DD + h * HD;
        const __half* vp = v + ((size_t)b * NN) * DD + h * HD;
#pragma unroll
        for (int i = 0; i < 4; i++) {
            int idx = tid + i * 128;
            int row = idx >> 3, c8 = idx & 7;
            cp16(kBase[0] + row * 144 + c8 * 16, kp + (size_t)row * DD + c8 * 8);
            cp16(vBase[0] + row * 144 + c8 * 16, vp + (size_t)row * DD + c8 * 8);
        }
        cp_commit();
    }
    cp_wait<0>();
    __syncthreads();

    // ---- Q fragments via ldmatrix, pre-scaled by 1/8 (exact in fp16) ----
    uint32_t qa[4][4];
    {
        const uint32_t qRow = (uint32_t)(wid * 16 + (lane & 15));
        const uint32_t qCol = (uint32_t)((lane >> 4) << 2);
        __half2 sch = __float2half2_rn(0.125f);
        uint32_t scu = *reinterpret_cast<uint32_t*>(&sch);
#pragma unroll
        for (int ks = 0; ks < 4; ks++) {
            ldmatrix_x4(qa[ks], qBase + (qRow * ARS + ks * 8 + qCol) * 4);
#pragma unroll
            for (int j = 0; j < 4; j++) qa[ks][j] = hmul2u(qa[ks][j], scu);
        }
    }

    float m0 = -1e30f, m1 = -1e30f, l0 = 0.f, l1 = 0.f;
    float oacc[8][4];
#pragma unroll
    for (int nt = 0; nt < 8; nt++)
#pragma unroll
        for (int r = 0; r < 4; r++) oacc[nt][r] = 0.f;

    const uint32_t kbRow = (uint32_t)(lane & 7);
    const uint32_t kbCol = (uint32_t)((lane >> 3) << 2);

    for (int t = 0; t < NN / 64; t++) {
        const int buf = t & 1;
        // issue next K/V tile (other buffer; computed 2 iters ago -> safe)
        if (t + 1 < NN / 64) {
            const int nb = buf ^ 1;
            const __half* kp = k + ((size_t)(b * NN + (t + 1) * 64)) * DD + h * HD;
            const __half* vp = v + ((size_t)(b * NN + (t + 1) * 64)) * DD + h * HD;
#pragma unroll
            for (int i = 0; i < 4; i++) {
                int idx = tid + i * 128;
                int row = idx >> 3, c8 = idx & 7;
                cp16(kBase[nb] + row * 144 + c8 * 16, kp + (size_t)row * DD + c8 * 8);
                cp16(vBase[nb] + row * 144 + c8 * 16, vp + (size_t)row * DD + c8 * 8);
            }
        }
        cp_commit();

        // ---- S = Q K^T (K fragments via ldmatrix) ----
        float s[8][4];
#pragma unroll
        for (int nt = 0; nt < 8; nt++)
#pragma unroll
            for (int r = 0; r < 4; r++) s[nt][r] = 0.f;
#pragma unroll
        for (int nt = 0; nt < 8; nt++) {
            uint32_t bq0[4], bq1[4];
            uint32_t base = kBase[buf] + ((kbRow + nt * 8) * ARS + kbCol) * 4;
            ldmatrix_x4(bq0, base);
            ldmatrix_x4(bq1, base + 16 * 4);
            mma16(s[nt], qa[0], &bq0[0]);
            mma16(s[nt], qa[1], &bq0[2]);
            mma16(s[nt], qa[2], &bq1[0]);
            mma16(s[nt], qa[3], &bq1[2]);
        }

        // ---- online softmax ----
        float mx0 = -1e30f, mx1 = -1e30f;
#pragma unroll
        for (int nt = 0; nt < 8; nt++) {
            mx0 = fmaxf(mx0, fmaxf(s[nt][0], s[nt][1]));
            mx1 = fmaxf(mx1, fmaxf(s[nt][2], s[nt][3]));
        }
        mx0 = fmaxf(mx0, __shfl_xor_sync(0xffffffffu, mx0, 1));
        mx0 = fmaxf(mx0, __shfl_xor_sync(0xffffffffu, mx0, 2));
        mx1 = fmaxf(mx1, __shfl_xor_sync(0xffffffffu, mx1, 1));
        mx1 = fmaxf(mx1, __shfl_xor_sync(0xffffffffu, mx1, 2));
        float mn0 = fmaxf(m0, mx0), mn1 = fmaxf(m1, mx1);
        float a0 = __expf(m0 - mn0), a1 = __expf(m1 - mn1);
        m0 = mn0; m1 = mn1;
        float sum0 = 0.f, sum1 = 0.f;
#pragma unroll
        for (int nt = 0; nt < 8; nt++) {
            s[nt][0] = __expf(s[nt][0] - m0);
            s[nt][1] = __expf(s[nt][1] - m0);
            s[nt][2] = __expf(s[nt][2] - m1);
            s[nt][3] = __expf(s[nt][3] - m1);
            sum0 += s[nt][0] + s[nt][1];
            sum1 += s[nt][2] + s[nt][3];
        }
        sum0 += __shfl_xor_sync(0xffffffffu, sum0, 1);
        sum0 += __shfl_xor_sync(0xffffffffu, sum0, 2);
        sum1 += __shfl_xor_sync(0xffffffffu, sum1, 1);
        sum1 += __shfl_xor_sync(0xffffffffu, sum1, 2);
        l0 = l0 * a0 + sum0;
        l1 = l1 * a1 + sum1;
#pragma unroll
        for (int nt = 0; nt < 8; nt++) {
            oacc[nt][0] *= a0; oacc[nt][1] *= a0;
            oacc[nt][2] *= a1; oacc[nt][3] *= a1;
        }

        // ---- O += P V ----
#pragma unroll
        for (int ks = 0; ks < 4; ks++) {
            uint32_t pa[4];
            pa[0] = pack2h(s[2 * ks][0],     s[2 * ks][1]);
            pa[1] = pack2h(s[2 * ks][2],     s[2 * ks][3]);
            pa[2] = pack2h(s[2 * ks + 1][0], s[2 * ks + 1][1]);
            pa[3] = pack2h(s[2 * ks + 1][2], s[2 * ks + 1][3]);
#pragma unroll
            for (int ntp = 0; ntp < 4; ntp++) {
                uint32_t vb[4];
                uint32_t addr = vBase[buf] +
                    ((16 * ks + (lane & 15)) * ARS + 8 * ntp + ((lane >> 4) << 2)) * 4;
                ldmatrix_x4_trans(vb, addr);
                mma16(oacc[2 * ntp],     pa, vb);
                mma16(oacc[2 * ntp + 1], pa, vb + 2);
            }
        }
        cp_wait<0>();
        __syncthreads();
    }

    // ---- normalize + store (fp16) ----
    float r0 = 1.f / l0, r1 = 1.f / l1;
    int row0 = b * QQ + q0 + wid * 16 + gid;
#pragma unroll
    for (int nt = 0; nt < 8; nt++) {
        int col = h * HD + nt * 8 + tg * 2;
        *reinterpret_cast<uint32_t*>(&o[(size_t)row0 * DD + col]) =
            pack2h(oacc[nt][0] * r0, oacc[nt][1] * r0);
        *reinterpret_cast<uint32_t*>(&o[(size_t)(row0 + 8) * DD + col]) =
            pack2h(oacc[nt][2] * r1, oacc[nt][3] * r1);
    }
}

// ---------------------------------------------------------------------------
extern "C" void kernel_launch(void* const* d_in, const int* in_sizes, int n_in,
                              void* d_out, int out_size)
{
    const float* sources = (const float*)d_in[0];
    const float* queries = (const float*)d_in[1];
    const float* w_in    = (const float*)d_in[2];
    const float* b_in    = (const float*)d_in[3];
    const float* w_out   = (const float*)d_in[4];
    const float* b_out   = (const float*)d_in[5];
    float* out = (float*)d_out;

    __half *pqh, *pkh, *pvh, *poh, *psrch, *pqryh, *pwh, *pwoh;
    cudaGetSymbolAddress((void**)&pqh,   g_qh);
    cudaGetSymbolAddress((void**)&pkh,   g_kh);
    cudaGetSymbolAddress((void**)&pvh,   g_vh);
    cudaGetSymbolAddress((void**)&poh,   g_oh);
    cudaGetSymbolAddress((void**)&psrch, g_srch);
    cudaGetSymbolAddress((void**)&pqryh, g_qryh);
    cudaGetSymbolAddress((void**)&pwh,   g_wh);
    cudaGetSymbolAddress((void**)&pwoh,  g_woh);

    cudaFuncSetAttribute(gemm_h2<true,false>,  cudaFuncAttributeMaxDynamicSharedMemorySize, SMEM_GEMM);
    cudaFuncSetAttribute(gemm_h2<false,true>,  cudaFuncAttributeMaxDynamicSharedMemorySize, SMEM_GEMM);
    cudaFuncSetAttribute(attn_h2, cudaFuncAttributeMaxDynamicSharedMemorySize, SMEM_ATTN);

    // convert inputs to fp16
    cvt_f2h<<<(MQ * DD / 4 + 255) / 256, 256>>>(queries, pqryh, MQ * DD);
    cvt_f2h<<<(MS * DD / 4 + 255) / 256, 256>>>(sources, psrch, MS * DD);
    cvt_f2h<<<(3 * DD * DD / 4 + 255) / 256, 256>>>(w_in, pwh, 3 * DD * DD);
    cvt_f2h<<<(DD * DD / 4 + 255) / 256, 256>>>(w_out, pwoh, DD * DD);

    // Q projection
    gemm_h2<true,false><<<dim3(DD / 128, MQ / 128), 256, SMEM_GEMM>>>(
        pqryh, pwh, b_in, nullptr, pqh, MQ, DD, DD);
    // K projection
    gemm_h2<true,false><<<dim3(DD / 128, MS / 128), 256, SMEM_GEMM>>>(
        psrch, pwh + DD * DD, b_in + DD, nullptr, pkh, MS, DD, DD);
    // V projection
    gemm_h2<true,false><<<dim3(DD / 128, MS / 128), 256, SMEM_GEMM>>>(
        psrch, pwh + 2 * DD * DD, b_in + 2 * DD, nullptr, pvh, MS, DD, DD);
    // attention
    attn_h2<<<dim3(QQ / 64, BB * HH), 128, SMEM_ATTN>>>(pqh, pkh, pvh, poh);
    // out projection + bias + residual (fp32 out)
    gemm_h2<false,true><<<dim3(DD / 128, MQ / 128), 256, SMEM_GEMM>>>(
        poh, pwoh, b_out, queries, out, MQ, DD, DD);
}